// round 5
// baseline (speedup 1.0000x reference)
#include <cuda_runtime.h>
#include <math.h>
#include <stdint.h>

#define THREADS 256
#define TILE_ROWS 256
#define TILE_FLOATS (TILE_ROWS * 7)      // 1792
#define TILE_BYTES (TILE_FLOATS * 4)     // 7168
#define STAGES 2
#define NBLK 296

__device__ __forceinline__ void mbar_wait(uint32_t addr, int parity) {
    asm volatile(
        "{\n\t.reg .pred P;\n\t"
        "W_%=:\n\t"
        "mbarrier.try_wait.parity.acquire.cta.shared::cta.b64 P, [%0], %1;\n\t"
        "@!P bra W_%=;\n\t}"
        :: "r"(addr), "r"(parity) : "memory");
}

__global__ __launch_bounds__(THREADS)
void emotion_kernel(const float* __restrict__ rep,
                    const float* __restrict__ emo,
                    const float* __restrict__ WQ,
                    const float* __restrict__ WK,
                    const float* __restrict__ WD,
                    const float* __restrict__ bD,
                    float* __restrict__ out,
                    int nrows)
{
    __shared__ __align__(16) float sRep[STAGES][TILE_FLOATS];
    __shared__ __align__(16) float sEmo[STAGES][TILE_FLOATS];
    __shared__ __align__(16) float sOut[STAGES][TILE_FLOATS];
    __shared__ __align__(16) float sM[56];   // M = W_Q^T @ W_K, padded 7x8
    __shared__ __align__(16) float sCW[8];   // colsum(W_D)[0..6], [7]=sum(b_D)
    __shared__ __align__(8) unsigned long long mb_full[STAGES];
    __shared__ __align__(8) unsigned long long mb_empty[STAGES];

    const int tid = threadIdx.x;
    const int bid = blockIdx.x;
    const long long ntiles = ((long long)nrows + TILE_ROWS - 1) / TILE_ROWS;

    uint32_t a_full[STAGES], a_empty[STAGES], a_rep[STAGES], a_emo[STAGES], a_out[STAGES];
    #pragma unroll
    for (int s = 0; s < STAGES; ++s) {
        a_full[s]  = (uint32_t)__cvta_generic_to_shared(&mb_full[s]);
        a_empty[s] = (uint32_t)__cvta_generic_to_shared(&mb_empty[s]);
        a_rep[s]   = (uint32_t)__cvta_generic_to_shared(sRep[s]);
        a_emo[s]   = (uint32_t)__cvta_generic_to_shared(sEmo[s]);
        a_out[s]   = (uint32_t)__cvta_generic_to_shared(sOut[s]);
    }

    if (tid == 0) {
        #pragma unroll
        for (int s = 0; s < STAGES; ++s) {
            asm volatile("mbarrier.init.shared::cta.b64 [%0], 1;"  :: "r"(a_full[s])  : "memory");
            asm volatile("mbarrier.init.shared::cta.b64 [%0], %1;" :: "r"(a_empty[s]), "r"(THREADS) : "memory");
        }
    }

    // ---- per-block constant precompute ----
    if (tid < 49) {
        int j = tid / 7, k = tid % 7;
        float acc = 0.f;
        #pragma unroll
        for (int i = 0; i < 7; ++i) acc = fmaf(WQ[i * 7 + j], WK[i * 7 + k], acc);
        sM[j * 8 + k] = acc;
    } else if (tid < 56) {
        int k = tid - 49;
        float acc = 0.f;
        #pragma unroll
        for (int j = 0; j < 7; ++j) acc += WD[j * 7 + k];
        sCW[k] = acc;
    } else if (tid == 56) {
        float acc = 0.f;
        #pragma unroll
        for (int i = 0; i < 7; ++i) acc += bD[i];
        sCW[7] = acc;
    } else if (tid == 57) {
        sM[7] = 0.f;  // pad lanes (unused but keep defined)
    }
    __syncthreads();   // barriers + constants visible

    // ---- prologue: fill the pipeline ----
    if (tid == 0) {
        #pragma unroll
        for (int s = 0; s < STAGES; ++s) {
            long long tl = (long long)bid + (long long)s * NBLK;
            if (tl < ntiles && (tl + 1) * TILE_ROWS <= (long long)nrows) {
                asm volatile("mbarrier.arrive.expect_tx.shared::cta.b64 _, [%0], %1;"
                             :: "r"(a_full[s]), "r"(2 * TILE_BYTES) : "memory");
                const float* grep = rep + tl * TILE_FLOATS;
                const float* gemo = emo + tl * TILE_FLOATS;
                asm volatile("cp.async.bulk.shared::cluster.global.mbarrier::complete_tx::bytes "
                             "[%0], [%1], %2, [%3];"
                             :: "r"(a_rep[s]), "l"(grep), "r"(TILE_BYTES), "r"(a_full[s]) : "memory");
                asm volatile("cp.async.bulk.shared::cluster.global.mbarrier::complete_tx::bytes "
                             "[%0], [%1], %2, [%3];"
                             :: "r"(a_emo[s]), "l"(gemo), "r"(TILE_BYTES), "r"(a_full[s]) : "memory");
            }
        }
    }

    const float4* sM4  = (const float4*)sM;
    const float4* sCW4 = (const float4*)sCW;

    // ---- main persistent loop ----
    int it = 0;
    for (long long tl = bid; tl < ntiles; tl += NBLK, ++it) {
        const int st = it & 1;
        const int ph = (it >> 1) & 1;
        const long long row0 = tl * TILE_ROWS;
        const bool fulltile = (row0 + TILE_ROWS) <= (long long)nrows;

        if (fulltile) {
            mbar_wait(a_full[st], ph);

            const int base = tid * 7;
            float r[7], e[7];
            #pragma unroll
            for (int j = 0; j < 7; ++j) {
                r[j] = sRep[st][base + j];
                e[j] = sEmo[st][base + j];
            }
            // in-buffers consumed
            asm volatile("mbarrier.arrive.shared::cta.b64 _, [%0];" :: "r"(a_empty[st]) : "memory");

            // t = e_row @ M  (M rows read as float4 broadcasts)
            float t[7];
            #pragma unroll
            for (int k = 0; k < 7; ++k) t[k] = 0.f;
            #pragma unroll
            for (int j = 0; j < 7; ++j) {
                float4 m0 = sM4[j * 2 + 0];
                float4 m1 = sM4[j * 2 + 1];
                float ej = e[j];
                t[0] = fmaf(ej, m0.x, t[0]);
                t[1] = fmaf(ej, m0.y, t[1]);
                t[2] = fmaf(ej, m0.z, t[2]);
                t[3] = fmaf(ej, m0.w, t[3]);
                t[4] = fmaf(ej, m1.x, t[4]);
                t[5] = fmaf(ej, m1.y, t[5]);
                t[6] = fmaf(ej, m1.z, t[6]);
            }
            float raw[7];
            #pragma unroll
            for (int k = 0; k < 7; ++k) raw[k] = r[k] * t[k];
            float mx = raw[0];
            #pragma unroll
            for (int k = 1; k < 7; ++k) mx = fmaxf(mx, raw[k]);
            float p[7], sum = 0.f;
            #pragma unroll
            for (int k = 0; k < 7; ++k) { p[k] = __expf(raw[k] - mx); sum += p[k]; }
            float inv = __fdividef(1.f, sum);

            float4 c0 = sCW4[0];
            float4 c1 = sCW4[1];
            float cw[7] = {c0.x, c0.y, c0.z, c0.w, c1.x, c1.y, c1.z};
            float cb = c1.w;

            float o[7];
            #pragma unroll
            for (int k = 0; k < 7; ++k) {
                float s  = p[k] * inv;
                float s3 = s * s * s;
                float d  = fmaf(s3, cw[k], cb);
                d = fminf(1.f, fmaxf(-1.f, d));
                o[k] = r[k] + d;
            }

            // gate reuse of sOut[st]: store from 2 iterations ago must have read smem
            if (tid == 0) {
                asm volatile("cp.async.bulk.wait_group.read 1;" ::: "memory");
            }
            __syncthreads();

            #pragma unroll
            for (int j = 0; j < 7; ++j) sOut[st][base + j] = o[j];

            asm volatile("fence.proxy.async.shared::cta;" ::: "memory");
            __syncthreads();

            if (tid == 0) {
                float* gdst = out + row0 * 7;
                asm volatile("cp.async.bulk.global.shared::cta.bulk_group [%0], [%1], %2;"
                             :: "l"(gdst), "r"(a_out[st]), "r"(TILE_BYTES) : "memory");
                asm volatile("cp.async.bulk.commit_group;" ::: "memory");

                // issue load for tile tl + STAGES*NBLK into this stage
                long long tln = tl + (long long)STAGES * NBLK;
                if (tln < ntiles && (tln + 1) * TILE_ROWS <= (long long)nrows) {
                    mbar_wait(a_empty[st], (it >> 1) & 1);
                    asm volatile("mbarrier.arrive.expect_tx.shared::cta.b64 _, [%0], %1;"
                                 :: "r"(a_full[st]), "r"(2 * TILE_BYTES) : "memory");
                    const float* grep = rep + tln * TILE_FLOATS;
                    const float* gemo = emo + tln * TILE_FLOATS;
                    asm volatile("cp.async.bulk.shared::cluster.global.mbarrier::complete_tx::bytes "
                                 "[%0], [%1], %2, [%3];"
                                 :: "r"(a_rep[st]), "l"(grep), "r"(TILE_BYTES), "r"(a_full[st]) : "memory");
                    asm volatile("cp.async.bulk.shared::cluster.global.mbarrier::complete_tx::bytes "
                                 "[%0], [%1], %2, [%3];"
                                 :: "r"(a_emo[st]), "l"(gemo), "r"(TILE_BYTES), "r"(a_full[st]) : "memory");
                }
            }
        } else {
            // tail tile (last only): direct scalar path, no pipeline
            long long row = row0 + tid;
            if (row < (long long)nrows) {
                float r[7], e[7];
                #pragma unroll
                for (int j = 0; j < 7; ++j) {
                    r[j] = rep[row * 7 + j];
                    e[j] = emo[row * 7 + j];
                }
                float t[7];
                #pragma unroll
                for (int k = 0; k < 7; ++k) t[k] = 0.f;
                #pragma unroll
                for (int j = 0; j < 7; ++j) {
                    float ej = e[j];
                    #pragma unroll
                    for (int k = 0; k < 7; ++k)
                        t[k] = fmaf(ej, sM[j * 8 + k], t[k]);
                }
                float raw[7];
                #pragma unroll
                for (int k = 0; k < 7; ++k) raw[k] = r[k] * t[k];
                float mx = raw[0];
                #pragma unroll
                for (int k = 1; k < 7; ++k) mx = fmaxf(mx, raw[k]);
                float p[7], sum = 0.f;
                #pragma unroll
                for (int k = 0; k < 7; ++k) { p[k] = __expf(raw[k] - mx); sum += p[k]; }
                float inv = __fdividef(1.f, sum);
                #pragma unroll
                for (int k = 0; k < 7; ++k) {
                    float s  = p[k] * inv;
                    float s3 = s * s * s;
                    float d  = fmaf(s3, sCW[k], sCW[7]);
                    d = fminf(1.f, fmaxf(-1.f, d));
                    out[row * 7 + k] = r[k] + d;
                }
            }
        }
    }

    // drain outstanding bulk stores before block exit
    if (tid == 0) {
        asm volatile("cp.async.bulk.wait_group 0;" ::: "memory");
    }
}

extern "C" void kernel_launch(void* const* d_in, const int* in_sizes, int n_in,
                              void* d_out, int out_size)
{
    const float* rep = (const float*)d_in[0];
    const float* emo = (const float*)d_in[1];
    const float* WQ  = (const float*)d_in[2];
    const float* WK  = (const float*)d_in[3];
    const float* WD  = (const float*)d_in[4];
    const float* bD  = (const float*)d_in[5];
    float* out = (float*)d_out;

    int nrows = in_sizes[0] / 7;
    long long ntiles = ((long long)nrows + TILE_ROWS - 1) / TILE_ROWS;
    int grid = (int)((ntiles < NBLK) ? ntiles : NBLK);

    emotion_kernel<<<grid, THREADS>>>(rep, emo, WQ, WK, WD, bD, out, nrows);
}